// round 13
// baseline (speedup 1.0000x reference)
#include <cuda_runtime.h>
#include <cuda_fp16.h>
#include <cstdint>

// Problem constants: E=8, OUT=4096, IN=1024, B=16, S=2048
#define NB   16
#define NS   2048
#define NIN  1024
#define NOUT 4096
#define NE   8

// Device scratch (no allocations allowed): routing + fp16 copies.
__device__ int g_expert_idx[NB];
__device__ __half g_x_h[(size_t)NB * NS * NIN];     // 64 MB
__device__ __half g_w_h[(size_t)NE * NOUT * NIN];   // 64 MB

// ---------------------------------------------------------------------------
// PTX helpers (target-neutral: cp.async / ldmatrix / mma.sync fp16)
// ---------------------------------------------------------------------------
__device__ __forceinline__ uint32_t smem_u32(const void* p) {
    uint32_t a;
    asm("{ .reg .u64 t; cvta.to.shared.u64 t, %1; cvt.u32.u64 %0, t; }"
        : "=r"(a) : "l"(p));
    return a;
}

__device__ __forceinline__ void cp16(uint32_t dst, const void* src) {
    asm volatile("cp.async.cg.shared.global [%0], [%1], 16;" :: "r"(dst), "l"(src));
}
#define CP_COMMIT()   asm volatile("cp.async.commit_group;" ::: "memory")
#define CP_WAIT_1()   asm volatile("cp.async.wait_group 1;" ::: "memory")

__device__ __forceinline__ void ldsm_x4(uint32_t* r, uint32_t a) {
    asm volatile("ldmatrix.sync.aligned.m8n8.x4.shared.b16 {%0,%1,%2,%3}, [%4];"
                 : "=r"(r[0]), "=r"(r[1]), "=r"(r[2]), "=r"(r[3]) : "r"(a));
}

// fp16 MMA, fp32 accumulate: m16n8k16.
__device__ __forceinline__ void mma_f16(float* d, const uint32_t* a, const uint32_t* b) {
    asm volatile(
        "mma.sync.aligned.m16n8k16.row.col.f32.f16.f16.f32 "
        "{%0,%1,%2,%3}, {%4,%5,%6,%7}, {%8,%9}, {%0,%1,%2,%3};"
        : "+f"(d[0]), "+f"(d[1]), "+f"(d[2]), "+f"(d[3])
        : "r"(a[0]), "r"(a[1]), "r"(a[2]), "r"(a[3]), "r"(b[0]), "r"(b[1]));
}

// ---------------------------------------------------------------------------
// Kernel: top-1 routing (+ optional idx tail in output)
// ---------------------------------------------------------------------------
__global__ void route_kernel(const float* __restrict__ probs,
                             float* __restrict__ out_tail, int n_tail) {
    int b = threadIdx.x;
    if (b < NB) {
        const float* p = probs + b * NE;
        float best = p[0];
        int bi = 0;
#pragma unroll
        for (int e = 1; e < NE; e++) {
            float v = p[e];
            if (v > best) { best = v; bi = e; }
        }
        g_expert_idx[b] = bi;
        if (out_tail != nullptr && b < n_tail) out_tail[b] = (float)bi;
    }
}

// ---------------------------------------------------------------------------
// Kernel: fp32 -> fp16 conversion pre-pass (RN, unbiased).
// ---------------------------------------------------------------------------
__global__ void f16_convert_kernel(const float4* __restrict__ src, int n4, int which) {
    int i = blockIdx.x * blockDim.x + threadIdx.x;
    if (i >= n4) return;
    __half2* dst = (__half2*)(which ? g_w_h : g_x_h);
    float4 v = src[i];
    dst[2 * i + 0] = __floats2half2_rn(v.x, v.y);
    dst[2 * i + 1] = __floats2half2_rn(v.z, v.w);
}

// ---------------------------------------------------------------------------
// FP16 GEMM (fp32 accumulate), 64x128 tile, 128 threads (4 warps 1x4,
// warp tile 64x32), BK=64 fp16, 3-stage cp.async, XOR-swizzled smem,
// fragment double-buffering, 3 CTAs/SM (12 warps/SM).
//   C[b][m][n] = x[b][m][:] . W[e(b)][n][:] + bias[e(b)][n]
// ---------------------------------------------------------------------------
#define BM 64
#define BN 128
#define BK 64                       // fp16 elements -> 128B row, 8 x 16B chunks
#define STAGES 3
#define A_OFF 0
#define B_OFF 8192                  // A: 64 rows x 128B
#define STAGE_BYTES 24576           // + B: 128 rows x 128B
#define KBLOCKS (NIN / BK)          // 16

__global__ __launch_bounds__(128, 3)
void moe_f16_gemm(const float* __restrict__ bias_all,
                  float* __restrict__ out) {
    extern __shared__ char dyn_smem[];
    const uint32_t sbase = smem_u32(dyn_smem);

    const int tid = threadIdx.x;
    const int wid = tid >> 5;       // 0..3 = warp_n (32 cols each); all warps span 64 rows
    const int l   = tid & 31;

    const int b = blockIdx.z;
    const int e = g_expert_idx[b];
    const int block_row = blockIdx.y * BM;
    const int block_col = blockIdx.x * BN;

    const __half* __restrict__ Ag = g_x_h + (size_t)b * NS * NIN;
    const __half* __restrict__ Bg = g_w_h + (size_t)e * NOUT * NIN;

    // cp.async: A = 512 16B chunks (4/thread), B = 1024 (8/thread).
    // Swizzled store: chunk j of row r goes to chunk (j ^ (r&7)).
    auto load_stage = [&](int stage, int k0) {
        uint32_t sb = sbase + stage * STAGE_BYTES;
#pragma unroll
        for (int u = 0; u < 4; u++) {
            int c = tid + u * 128;
            int r = c >> 3, j = c & 7;
            uint32_t so = ((uint32_t)r << 7) + (uint32_t)((j ^ (r & 7)) << 4);
            cp16(sb + A_OFF + so, Ag + (size_t)(block_row + r) * NIN + k0 + j * 8);
        }
#pragma unroll
        for (int u = 0; u < 8; u++) {
            int c = tid + u * 128;
            int r = c >> 3, j = c & 7;
            uint32_t so = ((uint32_t)r << 7) + (uint32_t)((j ^ (r & 7)) << 4);
            cp16(sb + B_OFF + so, Bg + (size_t)(block_col + r) * NIN + k0 + j * 8);
        }
        CP_COMMIT();
    };

    // Accumulators: 4 m-tiles(16) x 4 n-tiles(8) x 4 = 64 regs
    float acc[4][4][4];
#pragma unroll
    for (int i = 0; i < 4; i++)
#pragma unroll
        for (int j = 0; j < 4; j++)
#pragma unroll
            for (int q = 0; q < 4; q++) acc[i][j][q] = 0.0f;

    // ldsm lane addressing (swizzled).  Lane rows satisfy row&7 == l&7, so the
    // swizzle is chunk ^ (l&7) — constant per lane.  One 16B chunk = 8 fp16 = k8.
    const uint32_t lx    = (uint32_t)(l & 7);
    const uint32_t a_row = (uint32_t)(l & 15);                            // + mt*16
    const uint32_t a_hi  = (uint32_t)((l >> 4) & 1);                      // k8-half
    const uint32_t b_row = (uint32_t)(wid * 32 + (l & 7) + (((l >> 4) & 1) << 3)); // + np*16
    const uint32_t b_hi  = (uint32_t)((l >> 3) & 1);

    // Fragment buffers (double-buffered across k16-steps)
    uint32_t af[2][4][4], bf[2][4][2];

    auto ld_frags = [&](uint32_t sb, int ks, int buf) {
        const uint32_t ac = (uint32_t)(2 * ks) + a_hi;   // 2 chunks per k16-step
        const uint32_t bc = (uint32_t)(2 * ks) + b_hi;
        const uint32_t a_base = sb + A_OFF + (a_row << 7) + ((ac ^ lx) << 4);
        const uint32_t b_base = sb + B_OFF + (b_row << 7) + ((bc ^ lx) << 4);
#pragma unroll
        for (int mt = 0; mt < 4; mt++)
            ldsm_x4(af[buf][mt], a_base + mt * (16 << 7));
#pragma unroll
        for (int np = 0; np < 2; np++) {
            uint32_t t[4];
            ldsm_x4(t, b_base + np * (16 << 7));
            bf[buf][2 * np + 0][0] = t[0]; bf[buf][2 * np + 0][1] = t[1];
            bf[buf][2 * np + 1][0] = t[2]; bf[buf][2 * np + 1][1] = t[3];
        }
    };

    // Prologue: stages 0,1 in flight
    load_stage(0, 0);
    load_stage(1, BK);

    for (int kb = 0; kb < KBLOCKS; kb++) {
        CP_WAIT_1();            // stage kb complete
        __syncthreads();        // loads visible; buffer (kb+2)%3 free

        if (kb + 2 < KBLOCKS) load_stage((kb + 2) % STAGES, (kb + 2) * BK);
        else CP_COMMIT();       // keep group count uniform

        const uint32_t sb = sbase + (kb % STAGES) * STAGE_BYTES;

        ld_frags(sb, 0, 0);
#pragma unroll
        for (int ks = 0; ks < 4; ks++) {        // 4 x k16
            const int cur = ks & 1;
            if (ks < 3) ld_frags(sb, ks + 1, cur ^ 1);   // prefetch next k-step
#pragma unroll
            for (int mt = 0; mt < 4; mt++)
#pragma unroll
                for (int nt = 0; nt < 4; nt++)
                    mma_f16(acc[mt][nt], af[cur][mt], bf[cur][nt]);
        }
    }

    // ---- epilogue: bias + direct stores (64 rows x 32 cols per warp) ----
    const float* bias = bias_all + (size_t)e * NOUT;
    float* outb = out + (size_t)b * NS * NOUT;
    const int r0 = block_row + (l >> 2);
    const int c0 = block_col + wid * 32 + (l & 3) * 2;

#pragma unroll
    for (int nt = 0; nt < 4; nt++) {
        int cc = c0 + nt * 8;
        float2 bb = *(const float2*)(bias + cc);
#pragma unroll
        for (int mt = 0; mt < 4; mt++) {
            int rr = r0 + mt * 16;
            float2 v0 = { acc[mt][nt][0] + bb.x, acc[mt][nt][1] + bb.y };
            float2 v1 = { acc[mt][nt][2] + bb.x, acc[mt][nt][3] + bb.y };
            *(float2*)(outb + (size_t)rr * NOUT + cc)       = v0;
            *(float2*)(outb + (size_t)(rr + 8) * NOUT + cc) = v1;
        }
    }
}

// ---------------------------------------------------------------------------
// kernel_launch
// Inputs: x [B,S,IN] f32, expert_probs [B,E] f32,
//         expert_weights [E,OUT,IN] f32, expert_biases [E,OUT] f32
// ---------------------------------------------------------------------------
extern "C" void kernel_launch(void* const* d_in, const int* in_sizes, int n_in,
                              void* d_out, int out_size) {
    const float* x     = (const float*)d_in[0];
    const float* probs = (const float*)d_in[1];
    const float* w     = (const float*)d_in[2];
    const float* bias  = (const float*)d_in[3];
    float* out = (float*)d_out;

    const long long main_elems = (long long)NB * NS * NOUT;
    long long tail_ll = (long long)out_size - main_elems;
    int n_tail = 0;
    float* out_tail = nullptr;
    if (tail_ll > 0) {
        n_tail = (int)(tail_ll < NB ? tail_ll : NB);
        out_tail = out + main_elems;
    }

    // Convert x and W to fp16 (memory-bound, ~55 us)
    const int n4_x = (NB * NS * NIN) / 4;
    const int n4_w = (NE * NOUT * NIN) / 4;
    f16_convert_kernel<<<(n4_x + 255) / 256, 256>>>((const float4*)x, n4_x, 0);
    f16_convert_kernel<<<(n4_w + 255) / 256, 256>>>((const float4*)w, n4_w, 1);

    route_kernel<<<1, 32>>>(probs, out_tail, n_tail);

    const int dyn_smem = STAGES * STAGE_BYTES;   // 73,728 bytes (x3 CTAs = 216KB/SM)
    cudaFuncSetAttribute(moe_f16_gemm, cudaFuncAttributeMaxDynamicSharedMemorySize, dyn_smem);
    dim3 grid(NOUT / BN, NS / BM, NB);           // (32, 32, 16) = 16384 CTAs
    moe_f16_gemm<<<grid, 128, dyn_smem>>>(bias, out);
}